// round 4
// baseline (speedup 1.0000x reference)
#include <cuda_runtime.h>

// ---------------------------------------------------------------------------
// BigramTransformer forward, fp32 baseline.
// B=2048 T=64 D=128 H=4 HD=32 L=6 V=256 DFF=512
// ---------------------------------------------------------------------------

#define Bc   2048
#define Tc   64
#define Dc   128
#define Hc   4
#define HDc  32
#define Lc   6
#define Vc   256
#define DFFc 512
#define NTOK (Bc * Tc)          /* 131072 */
#define QKVC (3 * Dc)           /* 384    */

// ------------------------- scratch (device globals) ------------------------
__device__ float g_x   [(size_t)NTOK * Dc];
__device__ float g_h   [(size_t)NTOK * Dc];
__device__ float g_qkv [(size_t)NTOK * QKVC];
__device__ float g_att [(size_t)NTOK * Dc];
__device__ float g_mid [(size_t)NTOK * DFFc];
__device__ float g_wqkv[(size_t)Lc * Dc * QKVC];

// ------------------------- weight repack: [L,H,D,HD]x3 -> [L,D,3*D] --------
__global__ void repack_kernel(const float* __restrict__ Wq,
                              const float* __restrict__ Wk,
                              const float* __restrict__ Wv,
                              float* __restrict__ out)
{
    int i = blockIdx.x * blockDim.x + threadIdx.x;
    const int total = Lc * Hc * Dc * HDc;
    if (i >= total) return;
    int e = i % HDc;
    int d = (i / HDc) % Dc;
    int h = (i / (HDc * Dc)) % Hc;
    int l = i / (HDc * Dc * Hc);
    int src = ((l * Hc + h) * Dc + d) * HDc + e;
    size_t dst = ((size_t)l * Dc + d) * QKVC;
    int col = h * HDc + e;
    out[dst + col]            = Wq[src];
    out[dst + Dc + col]       = Wk[src];
    out[dst + 2 * Dc + col]   = Wv[src];
}

// ------------------------- embedding ---------------------------------------
__global__ void embed_kernel(const int* __restrict__ idx,
                             const float* __restrict__ tok,
                             const float* __restrict__ pos,
                             float* __restrict__ x)
{
    int n = blockIdx.x;        // token index 0..NTOK-1
    int d = threadIdx.x;       // 0..127
    int t = n & (Tc - 1);
    int v = idx[n];
    x[(size_t)n * Dc + d] = tok[v * Dc + d] + pos[t * Dc + d];
}

// ------------------------- layernorm (one block / token) --------------------
__global__ __launch_bounds__(Dc) void ln_kernel(const float* __restrict__ in,
                                                float* __restrict__ out,
                                                const float* __restrict__ gam,
                                                const float* __restrict__ bet)
{
    int n = blockIdx.x;
    int d = threadIdx.x;
    float x = in[(size_t)n * Dc + d];

    float s = x;
    #pragma unroll
    for (int o = 16; o > 0; o >>= 1) s += __shfl_xor_sync(0xffffffffu, s, o);
    __shared__ float ws[4];
    if ((d & 31) == 0) ws[d >> 5] = s;
    __syncthreads();
    float mean = (ws[0] + ws[1] + ws[2] + ws[3]) * (1.0f / Dc);

    float c = x - mean;
    float v = c * c;
    #pragma unroll
    for (int o = 16; o > 0; o >>= 1) v += __shfl_xor_sync(0xffffffffu, v, o);
    __shared__ float ws2[4];
    if ((d & 31) == 0) ws2[d >> 5] = v;
    __syncthreads();
    float var = (ws2[0] + ws2[1] + ws2[2] + ws2[3]) * (1.0f / Dc);

    out[(size_t)n * Dc + d] = c * rsqrtf(var + 1e-5f) * gam[d] + bet[d];
}

// ------------------------- generic SGEMM: C = act(A@W + bias) (+ res) -------
// A: [M,K] row-major, W: [K,N] row-major. M%64==0, N%64==0, K%16==0.
__global__ __launch_bounds__(256) void gemm_kernel(
    const float* __restrict__ A, const float* __restrict__ W,
    const float* __restrict__ bias, const float* __restrict__ res,
    float* __restrict__ C, int M, int N, int K, int relu)
{
    __shared__ float As[64][16];
    __shared__ float Ws[16][64];
    const int tid  = threadIdx.x;
    const int m0   = blockIdx.y * 64;
    const int n0   = blockIdx.x * 64;
    const int ty   = tid >> 4;           // 0..15
    const int tx   = tid & 15;           // 0..15
    const int arow = tid >> 2;           // 0..63
    const int acol = (tid & 3) << 2;     // 0,4,8,12
    const int wrow = tid >> 4;           // 0..15
    const int wcol = (tid & 15) << 2;    // 0..60

    float acc[4][4] = {};

    for (int k0 = 0; k0 < K; k0 += 16) {
        *(float4*)&As[arow][acol] =
            *(const float4*)(A + (size_t)(m0 + arow) * K + k0 + acol);
        *(float4*)&Ws[wrow][wcol] =
            *(const float4*)(W + (size_t)(k0 + wrow) * N + n0 + wcol);
        __syncthreads();
        #pragma unroll
        for (int k = 0; k < 16; k++) {
            float a[4];
            #pragma unroll
            for (int i = 0; i < 4; i++) a[i] = As[ty * 4 + i][k];
            float4 bv = *(const float4*)&Ws[k][tx * 4];
            #pragma unroll
            for (int i = 0; i < 4; i++) {
                acc[i][0] = fmaf(a[i], bv.x, acc[i][0]);
                acc[i][1] = fmaf(a[i], bv.y, acc[i][1]);
                acc[i][2] = fmaf(a[i], bv.z, acc[i][2]);
                acc[i][3] = fmaf(a[i], bv.w, acc[i][3]);
            }
        }
        __syncthreads();
    }

    const int n = n0 + tx * 4;
    float4 bb = make_float4(0.f, 0.f, 0.f, 0.f);
    if (bias) bb = *(const float4*)(bias + n);
    #pragma unroll
    for (int i = 0; i < 4; i++) {
        const size_t m = (size_t)(m0 + ty * 4 + i);
        float4 v = make_float4(acc[i][0] + bb.x, acc[i][1] + bb.y,
                               acc[i][2] + bb.z, acc[i][3] + bb.w);
        if (relu) {
            v.x = fmaxf(v.x, 0.f); v.y = fmaxf(v.y, 0.f);
            v.z = fmaxf(v.z, 0.f); v.w = fmaxf(v.w, 0.f);
        }
        if (res) {
            const float4 r = *(const float4*)(res + m * N + n);
            v.x += r.x; v.y += r.y; v.z += r.z; v.w += r.w;
        }
        *(float4*)(C + m * N + n) = v;
    }
}

// ------------------------- attention: one block per (b,h) -------------------
__global__ __launch_bounds__(Tc) void attn_kernel(const float* __restrict__ qkv,
                                                  float* __restrict__ att)
{
    __shared__ float4 qsm[Tc][HDc / 4];
    __shared__ float4 ksm[Tc][HDc / 4];
    __shared__ float4 vsm[Tc][HDc / 4];

    const int bh  = blockIdx.x;
    const int b   = bh >> 2;          // H = 4
    const int h   = bh & 3;
    const int tid = threadIdx.x;      // = row t, 0..63

    const float* row = qkv + ((size_t)(b * Tc + tid)) * QKVC + h * HDc;
    #pragma unroll
    for (int j = 0; j < 8; j++) {
        qsm[tid][j] = *(const float4*)(row + 4 * j);
        ksm[tid][j] = *(const float4*)(row + Dc + 4 * j);
        vsm[tid][j] = *(const float4*)(row + 2 * Dc + 4 * j);
    }
    __syncthreads();

    const int t = tid;
    float q[HDc];
    #pragma unroll
    for (int j = 0; j < 8; j++) {
        float4 f = qsm[t][j];
        q[4 * j] = f.x; q[4 * j + 1] = f.y; q[4 * j + 2] = f.z; q[4 * j + 3] = f.w;
    }

    const float scale = 0.17677669529663687f;   // 32^-0.5
    float sc[Tc];
    float mx = -1e30f;
    #pragma unroll
    for (int s = 0; s < Tc; s++) {
        float d = 0.f;
        #pragma unroll
        for (int j = 0; j < 8; j++) {
            float4 f = ksm[s][j];
            d = fmaf(q[4 * j],     f.x, d);
            d = fmaf(q[4 * j + 1], f.y, d);
            d = fmaf(q[4 * j + 2], f.z, d);
            d = fmaf(q[4 * j + 3], f.w, d);
        }
        d *= scale;
        sc[s] = d;
        if (s <= t) mx = fmaxf(mx, d);
    }

    float sum = 0.f;
    #pragma unroll
    for (int s = 0; s < Tc; s++) {
        float w = (s <= t) ? __expf(sc[s] - mx) : 0.f;
        sc[s] = w;
        sum += w;
    }
    const float inv = 1.f / sum;

    float4 acc[8] = {};
    #pragma unroll
    for (int s = 0; s < Tc; s++) {
        float w = sc[s];                       // 0 for masked s>t
        #pragma unroll
        for (int j = 0; j < 8; j++) {
            float4 f = vsm[s][j];
            acc[j].x = fmaf(w, f.x, acc[j].x);
            acc[j].y = fmaf(w, f.y, acc[j].y);
            acc[j].z = fmaf(w, f.z, acc[j].z);
            acc[j].w = fmaf(w, f.w, acc[j].w);
        }
    }

    float* outp = att + ((size_t)(b * Tc + t)) * Dc + h * HDc;
    #pragma unroll
    for (int j = 0; j < 8; j++) {
        float4 o = acc[j];
        o.x *= inv; o.y *= inv; o.z *= inv; o.w *= inv;
        *(float4*)(outp + 4 * j) = o;
    }
}

// ------------------------- launcher -----------------------------------------
extern "C" void kernel_launch(void* const* d_in, const int* in_sizes, int n_in,
                              void* d_out, int out_size)
{
    (void)in_sizes; (void)n_in; (void)out_size;
    const int*   idx  = (const int*)  d_in[0];
    const float* tok  = (const float*)d_in[1];
    const float* pos  = (const float*)d_in[2];
    const float* Wq   = (const float*)d_in[3];
    const float* Wk   = (const float*)d_in[4];
    const float* Wv   = (const float*)d_in[5];
    const float* Wo   = (const float*)d_in[6];
    const float* bo   = (const float*)d_in[7];
    const float* ln1g = (const float*)d_in[8];
    const float* ln1b = (const float*)d_in[9];
    const float* W1   = (const float*)d_in[10];
    const float* b1   = (const float*)d_in[11];
    const float* W2   = (const float*)d_in[12];
    const float* b2   = (const float*)d_in[13];
    const float* ln2g = (const float*)d_in[14];
    const float* ln2b = (const float*)d_in[15];
    const float* lnfg = (const float*)d_in[16];
    const float* lnfb = (const float*)d_in[17];
    const float* Wh   = (const float*)d_in[18];
    const float* bh   = (const float*)d_in[19];
    float* out = (float*)d_out;

    float *x, *h, *qkv, *att, *mid, *wqkv;
    cudaGetSymbolAddress((void**)&x,    g_x);
    cudaGetSymbolAddress((void**)&h,    g_h);
    cudaGetSymbolAddress((void**)&qkv,  g_qkv);
    cudaGetSymbolAddress((void**)&att,  g_att);
    cudaGetSymbolAddress((void**)&mid,  g_mid);
    cudaGetSymbolAddress((void**)&wqkv, g_wqkv);

    const int rp_total = Lc * Hc * Dc * HDc;
    repack_kernel<<<(rp_total + 255) / 256, 256>>>(Wq, Wk, Wv, wqkv);
    embed_kernel<<<NTOK, Dc>>>(idx, tok, pos, x);

    const dim3 gQKV (QKVC / 64, NTOK / 64);
    const dim3 gD   (Dc   / 64, NTOK / 64);
    const dim3 gFF  (DFFc / 64, NTOK / 64);
    const dim3 gV   (Vc   / 64, NTOK / 64);

    for (int l = 0; l < Lc; l++) {
        ln_kernel<<<NTOK, Dc>>>(x, h, ln1g + l * Dc, ln1b + l * Dc);
        gemm_kernel<<<gQKV, 256>>>(h, wqkv + (size_t)l * Dc * QKVC,
                                   nullptr, nullptr, qkv, NTOK, QKVC, Dc, 0);
        attn_kernel<<<Bc * Hc, Tc>>>(qkv, att);
        gemm_kernel<<<gD, 256>>>(att, Wo + (size_t)l * Dc * Dc,
                                 bo + l * Dc, x, x, NTOK, Dc, Dc, 0);
        ln_kernel<<<NTOK, Dc>>>(x, h, ln2g + l * Dc, ln2b + l * Dc);
        gemm_kernel<<<gFF, 256>>>(h, W1 + (size_t)l * Dc * DFFc,
                                  b1 + l * DFFc, nullptr, mid, NTOK, DFFc, Dc, 1);
        gemm_kernel<<<gD, 256>>>(mid, W2 + (size_t)l * DFFc * Dc,
                                 b2 + l * Dc, x, x, NTOK, Dc, DFFc, 0);
    }

    ln_kernel<<<NTOK, Dc>>>(x, h, lnfg, lnfb);
    gemm_kernel<<<gV, 256>>>(h, Wh, bh, nullptr, out, NTOK, Vc, Dc, 0);
}